// round 1
// baseline (speedup 1.0000x reference)
#include <cuda_runtime.h>
#include <math.h>

#define N_IMG 16
#define H 1024
#define W 1024
#define HW (H * W)              // 1048576
#define TOT (N_IMG * HW)        // 16777216
#define RAD 8
#define KLEN 17
#define NPASS 12
#define WW64 (W / 64)           // 16 uint64 words per row
#define WW32 (W / 32)           // 32 uint32 words per row

// ---------------- scratch (device globals; no allocations allowed) -------------
__device__ float g_t1[TOT];                       // row-blurred
__device__ float g_t2[TOT];                       // fully blurred
__device__ unsigned long long g_strong64[TOT / 64];
__device__ unsigned long long g_weak64[TOT / 64];
__device__ double g_acc;
__device__ int g_changed[NPASS];
__device__ float g_gw[KLEN];

// ---------------- init: gaussian weights (double, numpy-equivalent), zero accum -
__global__ void k_init() {
    if (threadIdx.x == 0) {
        double g[KLEN];
        double s = 0.0;
        for (int i = 0; i < KLEN; i++) {
            double d = (double)(i - RAD) / 2.0;   // SIGMA = 2.0
            g[i] = exp(-0.5 * d * d);
            s += g[i];
        }
        for (int i = 0; i < KLEN; i++) g_gw[i] = (float)(g[i] / s);
        g_acc = 0.0;
        for (int i = 0; i < NPASS; i++) g_changed[i] = 0;
    }
}

__device__ __forceinline__ int reflect_idx(int i, int n) {
    // numpy 'reflect' (no edge repeat); pad <= n-1 so single reflection suffices
    if (i < 0) return -i;
    if (i >= n) return 2 * n - 2 - i;
    return i;
}

// ---------------- row blur: grid (4, H, N), block 256 ---------------------------
__global__ void k_rowblur(const float* __restrict__ x) {
    __shared__ float sm[256 + 2 * RAD];
    __shared__ float w[KLEN];
    int tid = threadIdx.x;
    if (tid < KLEN) w[tid] = g_gw[tid];
    int j0 = blockIdx.x * 256;
    int row = blockIdx.y;
    int n = blockIdx.z;
    const float* src = x + ((size_t)n * HW + (size_t)row * W);
    for (int idx = tid; idx < 256 + 2 * RAD; idx += 256) {
        int gj = reflect_idx(j0 - RAD + idx, W);
        sm[idx] = src[gj];
    }
    __syncthreads();
    float acc = 0.f;
#pragma unroll
    for (int k = 0; k < KLEN; k++) acc += w[k] * sm[tid + k];
    g_t1[(size_t)n * HW + (size_t)row * W + j0 + tid] = acc;
}

// ---------------- col blur: grid (W/32, H/64, N), block (32,8) -------------------
__global__ void k_colblur() {
    __shared__ float sm[64 + 2 * RAD][32];
    __shared__ float w[KLEN];
    int tx = threadIdx.x, ty = threadIdx.y;
    int tid = ty * 32 + tx;
    if (tid < KLEN) w[tid] = g_gw[tid];
    int c0 = blockIdx.x * 32;
    int r0 = blockIdx.y * 64;
    int n = blockIdx.z;
    const float* src = g_t1 + (size_t)n * HW;
    for (int idx = tid; idx < (64 + 2 * RAD) * 32; idx += 256) {
        int rr = idx >> 5, cc = idx & 31;
        int gi = reflect_idx(r0 - RAD + rr, H);
        sm[rr][cc] = src[(size_t)gi * W + c0 + cc];
    }
    __syncthreads();
    float* dst = g_t2 + (size_t)n * HW;
#pragma unroll
    for (int s = 0; s < 8; s++) {
        int lr = ty * 8 + s;
        float acc = 0.f;
#pragma unroll
        for (int k = 0; k < KLEN; k++) acc += w[k] * sm[lr + k][tx];
        dst[(size_t)(r0 + lr) * W + c0 + tx] = acc;
    }
}

// ---------------- sobel + mag + NMS + thresholds: grid (W/32, H/16, N), block (32,16)
__global__ void k_sobel() {
    __shared__ float sm[20][36];   // smoothed, halo 2
    __shared__ float mg[18][34];   // magnitude, halo 1
    int tx = threadIdx.x, ty = threadIdx.y;
    int tid = ty * 32 + tx;
    int x0 = blockIdx.x * 32;
    int y0 = blockIdx.y * 16;
    int n = blockIdx.z;
    const float* src = g_t2 + (size_t)n * HW;

    for (int idx = tid; idx < 20 * 36; idx += 512) {
        int r = idx / 36, c = idx % 36;
        int gi = reflect_idx(y0 - 2 + r, H);
        int gj = reflect_idx(x0 - 2 + c, W);
        sm[r][c] = src[(size_t)gi * W + gj];
    }
    __syncthreads();

    for (int idx = tid; idx < 18 * 34; idx += 512) {
        int r = idx / 34, c = idx % 34;
        int gi = y0 - 1 + r, gj = x0 - 1 + c;
        float m = 0.f;
        if (gi >= 0 && gi < H && gj >= 0 && gj < W) {
            int sr = r + 1, sc = c + 1;
            float gx = (sm[sr - 1][sc + 1] - sm[sr - 1][sc - 1]) +
                       2.f * (sm[sr][sc + 1] - sm[sr][sc - 1]) +
                       (sm[sr + 1][sc + 1] - sm[sr + 1][sc - 1]);
            float gy = (sm[sr + 1][sc - 1] + 2.f * sm[sr + 1][sc] + sm[sr + 1][sc + 1]) -
                       (sm[sr - 1][sc - 1] + 2.f * sm[sr - 1][sc] + sm[sr - 1][sc + 1]);
            m = sqrtf(gx * gx + gy * gy);
        }
        mg[r][c] = m;
    }
    __syncthreads();

    // per-output-pixel NMS
    int sr = ty + 2, sc = tx + 2;
    float gx = (sm[sr - 1][sc + 1] - sm[sr - 1][sc - 1]) +
               2.f * (sm[sr][sc + 1] - sm[sr][sc - 1]) +
               (sm[sr + 1][sc + 1] - sm[sr + 1][sc - 1]);
    float gy = (sm[sr + 1][sc - 1] + 2.f * sm[sr + 1][sc] + sm[sr + 1][sc + 1]) -
               (sm[sr - 1][sc - 1] + 2.f * sm[sr - 1][sc] + sm[sr - 1][sc + 1]);

    // fold direction into [0,180): (u,v) with v>=0
    float u = gx, v = gy;
    if (v < 0.f) { u = -u; v = -v; }
    else if (v == 0.f && u < 0.f) { u = -u; }

    const float c1 = 0.41421356237309503f;  // tan 22.5
    const float c2 = 2.414213562373095f;    // tan 67.5
    int dy1, dx1, dy2, dx2;
    if (u > 0.f) {                            // ang in [0, 90)
        if (v < c1 * u)      { dy1 = 0;  dx1 = 1;  dy2 = 0; dx2 = -1; }  // b0
        else if (v < c2 * u) { dy1 = -1; dx1 = 1;  dy2 = 1; dx2 = -1; }  // b1
        else                 { dy1 = -1; dx1 = 0;  dy2 = 1; dx2 = 0;  }  // b2
    } else if (u < 0.f) {                     // ang in (90, 180)
        float t = -u;
        if (v <= c1 * t)     { dy1 = 0;  dx1 = 1;  dy2 = 0; dx2 = -1; }  // b0 (>=157.5)
        else if (v > c2 * t) { dy1 = -1; dx1 = 0;  dy2 = 1; dx2 = 0;  }  // b2 (<112.5)
        else                 { dy1 = -1; dx1 = -1; dy2 = 1; dx2 = 1;  }  // b3
    } else {                                  // u == 0: ang = 90 -> b2
        dy1 = -1; dx1 = 0; dy2 = 1; dx2 = 0;
    }

    float mc = mg[ty + 1][tx + 1];
    float n1 = mg[ty + 1 + dy1][tx + 1 + dx1];
    float n2 = mg[ty + 1 + dy2][tx + 1 + dx2];
    bool keep = (mc >= n1) && (mc >= n2);
    bool strong = keep && (mc > 0.2f);
    bool weak = keep && (mc > 0.1f);

    unsigned ws = __ballot_sync(0xffffffffu, strong);
    unsigned ww = __ballot_sync(0xffffffffu, weak);
    if (tx == 0) {
        size_t widx = (size_t)n * (HW / 32) + (size_t)(y0 + ty) * WW32 + blockIdx.x;
        reinterpret_cast<unsigned int*>(g_strong64)[widx] = ws;
        reinterpret_cast<unsigned int*>(g_weak64)[widx] = ww;
    }
}

// ---------------- hysteresis pass: grid (W/64, H/256, N), block 256 --------------
__global__ void k_hyst(int pass) {
    if (pass > 0 && g_changed[pass - 1] == 0) return;
    const int r = threadIdx.x;      // row within tile 0..255
    const int bx = blockIdx.x;      // word column 0..15
    const int ty = blockIdx.y;      // tile row 0..3
    const int n = blockIdx.z;

    __shared__ unsigned long long ss[258];
    __shared__ unsigned char lb[258], rb[258];

    unsigned long long* S = g_strong64 + (size_t)n * (HW / 64);
    const unsigned long long* Wk = g_weak64 + (size_t)n * (HW / 64);

    int gr = ty * 256 + r;
    unsigned long long wk = Wk[(size_t)gr * WW64 + bx];
    unsigned long long s0 = S[(size_t)gr * WW64 + bx];
    ss[r + 1] = s0;
    lb[r + 1] = (bx > 0)        ? (unsigned char)(S[(size_t)gr * WW64 + bx - 1] >> 63) : 0;
    rb[r + 1] = (bx < WW64 - 1) ? (unsigned char)(S[(size_t)gr * WW64 + bx + 1] & 1ULL) : 0;
    if (r == 0) {
        int ga = ty * 256 - 1;
        if (ga >= 0) {
            ss[0] = S[(size_t)ga * WW64 + bx];
            lb[0] = (bx > 0)        ? (unsigned char)(S[(size_t)ga * WW64 + bx - 1] >> 63) : 0;
            rb[0] = (bx < WW64 - 1) ? (unsigned char)(S[(size_t)ga * WW64 + bx + 1] & 1ULL) : 0;
        } else { ss[0] = 0ULL; lb[0] = 0; rb[0] = 0; }
    } else if (r == 1) {
        int gb = ty * 256 + 256;
        if (gb < H) {
            ss[257] = S[(size_t)gb * WW64 + bx];
            lb[257] = (bx > 0)        ? (unsigned char)(S[(size_t)gb * WW64 + bx - 1] >> 63) : 0;
            rb[257] = (bx < WW64 - 1) ? (unsigned char)(S[(size_t)gb * WW64 + bx + 1] & 1ULL) : 0;
        } else { ss[257] = 0ULL; lb[257] = 0; rb[257] = 0; }
    }
    __syncthreads();

    unsigned long long Lbit = (unsigned long long)((lb[r] | lb[r + 1] | lb[r + 2]) & 1);
    unsigned long long Rbit = ((unsigned long long)((rb[r] | rb[r + 1] | rb[r + 2]) & 1)) << 63;

    // local fixpoint: dilate(strong) & weak | strong, bit-parallel
    while (true) {
        unsigned long long up = ss[r];
        unsigned long long me = ss[r + 1];
        unsigned long long dn = ss[r + 2];
        unsigned long long vert = up | me | dn;
        unsigned long long d = vert | (vert << 1) | (vert >> 1) | Lbit | Rbit;
        unsigned long long ns = me | (d & wk);
        int ch = (ns != me);
        __syncthreads();
        if (ch) ss[r + 1] = ns;
        if (!__syncthreads_or(ch)) break;
    }

    unsigned long long fin = ss[r + 1];
    int tilech = __syncthreads_or(fin != s0);
    if (fin != s0) S[(size_t)gr * WW64 + bx] = fin;
    if (r == 0 && tilech) g_changed[pass] = 1;
}

// ---------------- loss reduction -------------------------------------------------
__global__ void k_loss(const float* __restrict__ y, const float* __restrict__ mask) {
    const unsigned int* S32 = reinterpret_cast<const unsigned int*>(g_strong64);
    float acc = 0.f;
    int stride = gridDim.x * blockDim.x;
    for (int idx = blockIdx.x * blockDim.x + threadIdx.x; idx < TOT; idx += stride) {
        unsigned int wbits = S32[idx >> 5];
        float e = (float)((wbits >> (idx & 31)) & 1u);
        float m = mask[idx & (HW - 1)];
        float yy = y[idx];
        acc += fabsf(e * m - yy * m);
    }
#pragma unroll
    for (int off = 16; off; off >>= 1) acc += __shfl_down_sync(0xffffffffu, acc, off);
    __shared__ float sred[32];
    int lane = threadIdx.x & 31, wid = threadIdx.x >> 5;
    if (lane == 0) sred[wid] = acc;
    __syncthreads();
    if (wid == 0) {
        acc = (lane < (int)(blockDim.x >> 5)) ? sred[lane] : 0.f;
#pragma unroll
        for (int off = 16; off; off >>= 1) acc += __shfl_down_sync(0xffffffffu, acc, off);
        if (lane == 0) atomicAdd(&g_acc, (double)acc);
    }
}

__global__ void k_fin(float* out) {
    if (threadIdx.x == 0) out[0] = (float)(g_acc * (1.0 / (double)HW));
}

// ---------------- launch ----------------------------------------------------------
extern "C" void kernel_launch(void* const* d_in, const int* in_sizes, int n_in,
                              void* d_out, int out_size) {
    const float* x = nullptr;
    const float* y = nullptr;
    const float* mask = nullptr;
    for (int i = 0; i < n_in; i++) {
        if (in_sizes[i] == HW && mask == nullptr) mask = (const float*)d_in[i];
        else if (x == nullptr) x = (const float*)d_in[i];
        else if (y == nullptr) y = (const float*)d_in[i];
    }

    k_init<<<1, 32>>>();
    k_rowblur<<<dim3(W / 256, H, N_IMG), 256>>>(x);
    k_colblur<<<dim3(W / 32, H / 64, N_IMG), dim3(32, 8)>>>();
    k_sobel<<<dim3(W / 32, H / 16, N_IMG), dim3(32, 16)>>>();
    for (int p = 0; p < NPASS; p++)
        k_hyst<<<dim3(W / 64, H / 256, N_IMG), 256>>>(p);
    k_loss<<<8192, 256>>>(y, mask);
    k_fin<<<1, 1>>>((float*)d_out);
}

// round 2
// speedup vs baseline: 1.4020x; 1.4020x over previous
#include <cuda_runtime.h>
#include <math.h>

#define N_IMG 16
#define H 1024
#define W 1024
#define HW (H * W)
#define TOT (N_IMG * HW)
#define RAD 8
#define KLEN 17
#define NPASS 12
#define WW64 (W / 64)
#define WW32 (W / 32)

// ---------------- scratch ----------------
__device__ float g_t1[TOT];
__device__ unsigned long long g_strong64[TOT / 64];
__device__ unsigned long long g_weak64[TOT / 64];
__device__ double g_acc;
__device__ int g_changed[NPASS];
__device__ float g_gw[KLEN];

__global__ void k_init() {
    if (threadIdx.x == 0) {
        double g[KLEN];
        double s = 0.0;
        for (int i = 0; i < KLEN; i++) {
            double d = (double)(i - RAD) / 2.0;
            g[i] = exp(-0.5 * d * d);
            s += g[i];
        }
        for (int i = 0; i < KLEN; i++) g_gw[i] = (float)(g[i] / s);
        g_acc = 0.0;
        for (int i = 0; i < NPASS; i++) g_changed[i] = 0;
    }
}

__device__ __forceinline__ int reflect_idx(int i, int n) {
    if (i < 0) return -i;
    if (i >= n) return 2 * n - 2 - i;
    return i;
}

// ---------------- row blur: grid (H, N), block 256, 4 px/thread ----------------
__global__ void k_rowblur(const float* __restrict__ x) {
    __shared__ __align__(16) float sm[W + 2 * RAD];
    __shared__ float w[KLEN];
    int tid = threadIdx.x;
    if (tid < KLEN) w[tid] = g_gw[tid];
    int row = blockIdx.x;
    int n = blockIdx.y;
    const float* src = x + ((size_t)n * HW + (size_t)row * W);
    reinterpret_cast<float4*>(sm + RAD)[tid] = reinterpret_cast<const float4*>(src)[tid];
    if (tid < RAD) {
        sm[tid] = src[RAD - tid];                 // reflect left
        sm[W + RAD + tid] = src[W - 2 - tid];     // reflect right
    }
    __syncthreads();
    int j = tid * 4;
    float r[20];
#pragma unroll
    for (int q = 0; q < 5; q++) {
        float4 v = *reinterpret_cast<const float4*>(sm + j + q * 4);
        r[q * 4 + 0] = v.x; r[q * 4 + 1] = v.y; r[q * 4 + 2] = v.z; r[q * 4 + 3] = v.w;
    }
    float a0 = 0.f, a1 = 0.f, a2 = 0.f, a3 = 0.f;
#pragma unroll
    for (int k = 0; k < KLEN; k++) {
        float wk = w[k];
        a0 += wk * r[k]; a1 += wk * r[k + 1]; a2 += wk * r[k + 2]; a3 += wk * r[k + 3];
    }
    float* dst = g_t1 + ((size_t)n * HW + (size_t)row * W);
    reinterpret_cast<float4*>(dst)[tid] = make_float4(a0, a1, a2, a3);
}

// ---------------- fused colblur + sobel + NMS + thresholds ----------------
// output tile 32 wide x 64 tall, block (32,8), grid (32, 16, 16)
#define T1R 84   // 64 + 2*(RAD+2)
#define T1C 36   // 32 + 4
#define SMR 68
#define SMC 36
#define MGR 66
#define MGC 34
__global__ void k_colsobel() {
    __shared__ float sA[T1R * T1C];   // t1 tile, later reused as magnitude
    __shared__ float sS[SMR * SMC];   // smoothed
    __shared__ signed char sB[64 * 32];
    __shared__ float w[KLEN];
    int tx = threadIdx.x, ty = threadIdx.y;
    int tid = ty * 32 + tx;
    if (tid < KLEN) w[tid] = g_gw[tid];
    int c0 = blockIdx.x * 32;
    int r0 = blockIdx.y * 64;
    int n = blockIdx.z;
    const float* src = g_t1 + (size_t)n * HW;

    // load t1 tile with reflect halo (rows r0-10 .. r0+73, cols c0-2 .. c0+33)
    for (int idx = tid; idx < T1R * T1C; idx += 256) {
        int rr = idx / T1C, cc = idx - rr * T1C;
        int gi = reflect_idx(r0 - (RAD + 2) + rr, H);
        int gj = reflect_idx(c0 - 2 + cc, W);
        sA[idx] = src[(size_t)gi * W + gj];
    }
    __syncthreads();

    // vertical blur -> smoothed (rows r0-2 .. r0+65, cols c0-2 .. c0+33)
    for (int idx = tid; idx < SMR * SMC; idx += 256) {
        float acc = 0.f;
#pragma unroll
        for (int k = 0; k < KLEN; k++) acc += w[k] * sA[idx + k * T1C];
        sS[idx] = acc;
    }
    __syncthreads();

    // magnitude (+ direction offset for interior centers), written into sA
    for (int idx = tid; idx < MGR * MGC; idx += 256) {
        int rr = idx / MGC, cc = idx - rr * MGC;
        int gi = r0 - 1 + rr, gj = c0 - 1 + cc;
        float m = 0.f, gx = 0.f, gy = 0.f;
        if ((unsigned)gi < (unsigned)H && (unsigned)gj < (unsigned)W) {
            const float* p = &sS[rr * SMC + cc];
            float a00 = p[0], a01 = p[1], a02 = p[2];
            float a10 = p[SMC], a12 = p[SMC + 2];
            float a20 = p[2 * SMC], a21 = p[2 * SMC + 1], a22 = p[2 * SMC + 2];
            gx = (a02 - a00) + 2.f * (a12 - a10) + (a22 - a20);
            gy = (a20 + 2.f * a21 + a22) - (a00 + 2.f * a01 + a02);
            m = sqrtf(gx * gx + gy * gy);
        }
        sA[idx] = m;
        if (rr >= 1 && rr <= 64 && cc >= 1 && cc <= 32) {
            float u = gx, v = gy;
            if (v < 0.f || (v == 0.f && u < 0.f)) { u = -u; v = -v; }
            const float c1 = 0.41421356237309503f;  // tan 22.5
            const float c2 = 2.414213562373095f;    // tan 67.5
            int off;
            if (u > 0.f) {
                if (v < c1 * u)      off = 1;            // b0 E/W
                else if (v < c2 * u) off = -(MGC - 1);   // b1 NE/SW
                else                 off = -MGC;         // b2 N/S
            } else if (u < 0.f) {
                float t = -u;
                if (v <= c1 * t)     off = 1;            // b0 (ang >= 157.5)
                else if (v > c2 * t) off = -MGC;         // b2 (ang < 112.5)
                else                 off = -(MGC + 1);   // b3 NW/SE
            } else {
                off = -MGC;                              // b2
            }
            sB[(rr - 1) * 32 + (cc - 1)] = (signed char)off;
        }
    }
    __syncthreads();

    // NMS + thresholds + bit pack; warp ty handles rows ty*8 .. ty*8+7
    unsigned int* S32 = reinterpret_cast<unsigned int*>(g_strong64);
    unsigned int* W32 = reinterpret_cast<unsigned int*>(g_weak64);
    size_t base = (size_t)n * (HW / 32) + (size_t)blockIdx.x;
#pragma unroll
    for (int s = 0; s < 8; s++) {
        int lr = ty * 8 + s;
        int ci = (lr + 1) * MGC + (tx + 1);
        float mc = sA[ci];
        int off = sB[lr * 32 + tx];
        float n1 = sA[ci + off];
        float n2 = sA[ci - off];
        bool keep = (mc >= n1) && (mc >= n2);
        bool strong = keep && (mc > 0.2f);
        bool weak = keep && (mc > 0.1f);
        unsigned ws = __ballot_sync(0xffffffffu, strong);
        unsigned ww = __ballot_sync(0xffffffffu, weak);
        if (tx == 0) {
            size_t widx = base + (size_t)(r0 + lr) * WW32;
            S32[widx] = ws;
            W32[widx] = ww;
        }
    }
}

// ---------------- hysteresis pass: grid (W/64, H/256, N), block 256 ----------------
__global__ void k_hyst(int pass) {
    if (pass > 0 && g_changed[pass - 1] == 0) return;
    const int r = threadIdx.x;
    const int bx = blockIdx.x;
    const int ty = blockIdx.y;
    const int n = blockIdx.z;

    __shared__ unsigned long long ss[258];
    __shared__ unsigned char lb[258], rb[258];

    unsigned long long* S = g_strong64 + (size_t)n * (HW / 64);
    const unsigned long long* Wk = g_weak64 + (size_t)n * (HW / 64);

    int gr = ty * 256 + r;
    unsigned long long wk = Wk[(size_t)gr * WW64 + bx];
    unsigned long long s0 = S[(size_t)gr * WW64 + bx];
    ss[r + 1] = s0;
    lb[r + 1] = (bx > 0)        ? (unsigned char)(S[(size_t)gr * WW64 + bx - 1] >> 63) : 0;
    rb[r + 1] = (bx < WW64 - 1) ? (unsigned char)(S[(size_t)gr * WW64 + bx + 1] & 1ULL) : 0;
    if (r == 0) {
        int ga = ty * 256 - 1;
        if (ga >= 0) {
            ss[0] = S[(size_t)ga * WW64 + bx];
            lb[0] = (bx > 0)        ? (unsigned char)(S[(size_t)ga * WW64 + bx - 1] >> 63) : 0;
            rb[0] = (bx < WW64 - 1) ? (unsigned char)(S[(size_t)ga * WW64 + bx + 1] & 1ULL) : 0;
        } else { ss[0] = 0ULL; lb[0] = 0; rb[0] = 0; }
    } else if (r == 1) {
        int gb = ty * 256 + 256;
        if (gb < H) {
            ss[257] = S[(size_t)gb * WW64 + bx];
            lb[257] = (bx > 0)        ? (unsigned char)(S[(size_t)gb * WW64 + bx - 1] >> 63) : 0;
            rb[257] = (bx < WW64 - 1) ? (unsigned char)(S[(size_t)gb * WW64 + bx + 1] & 1ULL) : 0;
        } else { ss[257] = 0ULL; lb[257] = 0; rb[257] = 0; }
    }
    __syncthreads();

    unsigned long long Lbit = (unsigned long long)((lb[r] | lb[r + 1] | lb[r + 2]) & 1);
    unsigned long long Rbit = ((unsigned long long)((rb[r] | rb[r + 1] | rb[r + 2]) & 1)) << 63;

    while (true) {
        unsigned long long up = ss[r];
        unsigned long long me = ss[r + 1];
        unsigned long long dn = ss[r + 2];
        unsigned long long vert = up | me | dn;
        unsigned long long d = vert | (vert << 1) | (vert >> 1) | Lbit | Rbit;
        unsigned long long ns = me | (d & wk);
        int ch = (ns != me);
        __syncthreads();
        if (ch) ss[r + 1] = ns;
        if (!__syncthreads_or(ch)) break;
    }

    unsigned long long fin = ss[r + 1];
    int tilech = __syncthreads_or(fin != s0);
    if (fin != s0) S[(size_t)gr * WW64 + bx] = fin;
    if (r == 0 && tilech) g_changed[pass] = 1;
}

// ---------------- loss: word-granular, vectorized ----------------
__global__ void k_loss(const float* __restrict__ y, const float* __restrict__ mask) {
    const unsigned int* S32 = reinterpret_cast<const unsigned int*>(g_strong64);
    float acc = 0.f;
    int nw = TOT / 32;
    int stride = gridDim.x * blockDim.x;
    for (int wi = blockIdx.x * blockDim.x + threadIdx.x; wi < nw; wi += stride) {
        unsigned int bits = S32[wi];
        int p = wi * 32;
        int mp = p & (HW - 1);
        const float4* y4 = reinterpret_cast<const float4*>(y + p);
        const float4* m4 = reinterpret_cast<const float4*>(mask + mp);
#pragma unroll
        for (int j = 0; j < 8; j++) {
            float4 yy = y4[j];
            float4 mm = m4[j];
            unsigned int b = bits >> (j * 4);
            acc += fabsf(((b & 1u) ? mm.x : 0.f) - yy.x * mm.x);
            acc += fabsf((((b >> 1) & 1u) ? mm.y : 0.f) - yy.y * mm.y);
            acc += fabsf((((b >> 2) & 1u) ? mm.z : 0.f) - yy.z * mm.z);
            acc += fabsf((((b >> 3) & 1u) ? mm.w : 0.f) - yy.w * mm.w);
        }
    }
#pragma unroll
    for (int off = 16; off; off >>= 1) acc += __shfl_down_sync(0xffffffffu, acc, off);
    __shared__ float sred[32];
    int lane = threadIdx.x & 31, wid = threadIdx.x >> 5;
    if (lane == 0) sred[wid] = acc;
    __syncthreads();
    if (wid == 0) {
        acc = (lane < (int)(blockDim.x >> 5)) ? sred[lane] : 0.f;
#pragma unroll
        for (int off = 16; off; off >>= 1) acc += __shfl_down_sync(0xffffffffu, acc, off);
        if (lane == 0) atomicAdd(&g_acc, (double)acc);
    }
}

__global__ void k_fin(float* out) {
    if (threadIdx.x == 0) out[0] = (float)(g_acc * (1.0 / (double)HW));
}

// ---------------- launch ----------------
extern "C" void kernel_launch(void* const* d_in, const int* in_sizes, int n_in,
                              void* d_out, int out_size) {
    const float* x = nullptr;
    const float* y = nullptr;
    const float* mask = nullptr;
    for (int i = 0; i < n_in; i++) {
        if (in_sizes[i] == HW && mask == nullptr) mask = (const float*)d_in[i];
        else if (x == nullptr) x = (const float*)d_in[i];
        else if (y == nullptr) y = (const float*)d_in[i];
    }

    k_init<<<1, 32>>>();
    k_rowblur<<<dim3(H, N_IMG), 256>>>(x);
    k_colsobel<<<dim3(W / 32, H / 64, N_IMG), dim3(32, 8)>>>();
    for (int p = 0; p < NPASS; p++)
        k_hyst<<<dim3(W / 64, H / 256, N_IMG), 256>>>(p);
    k_loss<<<2048, 256>>>(y, mask);
    k_fin<<<1, 1>>>((float*)d_out);
}